// round 5
// baseline (speedup 1.0000x reference)
#include <cuda_runtime.h>
#include <cstdint>

// out[nat, 48] = segment_sum(x*switch, src) - segment_sum(x*switch, dst)
// E = 1.6M, D = 48, nat = 50k.
// Strategy: stage 64 edges/CTA in SMEM (xw and -xw), then issue one
// 192-byte cp.reduce.async.bulk (TMA reduce, add.f32) per edge endpoint.
// Replaces 24 red.v4 ops/edge (atomic-op-rate bound) with 2 bulk reduces/edge.

#define D_FEAT 48
#define VECS_PER_EDGE 12          // 48 floats / 4
#define EPB 64                    // edges per block
#define F4_PER_BLOCK (EPB * VECS_PER_EDGE)   // 768

__global__ void __launch_bounds__(256)
scatter_bulk_kernel(const float4* __restrict__ x4,
                    const float* __restrict__ sw,
                    const int* __restrict__ esrc,
                    const int* __restrict__ edst,
                    float* __restrict__ out,
                    int n_edges) {
    __shared__ float4 s_pos[F4_PER_BLOCK];   // 12 KB:  xw
    __shared__ float4 s_neg[F4_PER_BLOCK];   // 12 KB: -xw

    int tid = threadIdx.x;
    int e0 = blockIdx.x * EPB;
    int m = n_edges - e0;                    // edges in this block
    if (m > EPB) m = EPB;
    int mf4 = m * VECS_PER_EDGE;

    // Load x, apply +/- switch, stage in SMEM (fully coalesced).
    #pragma unroll
    for (int k = 0; k < 3; k++) {
        int j = k * 256 + tid;               // 0..767
        if (j < mf4) {
            int el = j / VECS_PER_EDGE;      // local edge
            float s = __ldg(sw + e0 + el);
            float4 v = __ldcs(x4 + (size_t)(e0 + el) * VECS_PER_EDGE
                                   + (j - el * VECS_PER_EDGE));
            s_pos[j] = make_float4( v.x * s,  v.y * s,  v.z * s,  v.w * s);
            s_neg[j] = make_float4(-v.x * s, -v.y * s, -v.z * s, -v.w * s);
        }
    }
    __syncthreads();
    asm volatile("fence.proxy.async.shared::cta;" ::: "memory");

    // One 192B bulk-reduce per edge endpoint: threads 0..63 -> src(+),
    // threads 64..127 -> dst(-).
    if (tid < 2 * EPB) {
        int i = tid & (EPB - 1);
        if (i < m) {
            bool is_dst = tid >= EPB;
            int node = is_dst ? __ldg(edst + e0 + i) : __ldg(esrc + e0 + i);
            const float4* buf = is_dst ? (s_neg + i * VECS_PER_EDGE)
                                       : (s_pos + i * VECS_PER_EDGE);
            uint32_t saddr = (uint32_t)__cvta_generic_to_shared(buf);
            float* gaddr = out + (size_t)node * D_FEAT;
            asm volatile(
                "cp.reduce.async.bulk.global.shared::cta.bulk_group.add.f32 "
                "[%0], [%1], 192;"
                :: "l"(gaddr), "r"(saddr) : "memory");
            asm volatile("cp.async.bulk.commit_group;" ::: "memory");
            // SMEM must stay valid until TMA has read it; drain before exit.
            asm volatile("cp.async.bulk.wait_group.read 0;" ::: "memory");
        }
    }
}

extern "C" void kernel_launch(void* const* d_in, const int* in_sizes, int n_in,
                              void* d_out, int out_size) {
    const float4* x4  = (const float4*)d_in[0];   // x [E, 48] fp32
    const float*  sw  = (const float*)d_in[1];    // switch [E]
    const int*    src = (const int*)d_in[2];      // edge_src [E]
    const int*    dst = (const int*)d_in[3];      // edge_dst [E]
    float*        out = (float*)d_out;            // [nat, 48] fp32

    int n_edges = in_sizes[1];

    cudaMemsetAsync(out, 0, (size_t)out_size * sizeof(float));

    int n_blocks = (n_edges + EPB - 1) / EPB;     // 25000 for E=1.6M
    scatter_bulk_kernel<<<n_blocks, 256>>>(x4, sw, src, dst, out, n_edges);
}

// round 6
// speedup vs baseline: 1.0097x; 1.0097x over previous
#include <cuda_runtime.h>
#include <cstdint>

// out[nat, 48] = segment_sum(x*switch, src) - segment_sum(x*switch, dst)
// E = 1.6M, D = 48, nat = 50k.
// Hybrid dual-engine RMW delivery:
//   src(+) endpoint: red.global.add.v4.f32 directly from registers (LSU/L1tex path)
//   dst(-) endpoint: cp.reduce.async.bulk 192B from SMEM (TMA path)
// Each path carries 307 MB instead of one path carrying 614 MB, so the LTS
// RMW stream is fed by two independent per-SM engines.

#define D_FEAT 48
#define VECS_PER_EDGE 12                       // 48 floats / 4
#define EPB 64                                 // edges per block
#define F4_PER_BLOCK (EPB * VECS_PER_EDGE)     // 768 = 3 * 256

__device__ __forceinline__ void red_v4(float* p, float a, float b, float c, float d) {
    asm volatile("red.global.add.v4.f32 [%0], {%1,%2,%3,%4};"
                 :: "l"(p), "f"(a), "f"(b), "f"(c), "f"(d) : "memory");
}

__global__ void __launch_bounds__(256)
scatter_hybrid_kernel(const float4* __restrict__ x4,
                      const float* __restrict__ sw,
                      const int* __restrict__ esrc,
                      const int* __restrict__ edst,
                      float* __restrict__ out,
                      int n_edges) {
    __shared__ float4 s_neg[F4_PER_BLOCK];     // 12 KB: -xw for TMA dst reduce

    int tid = threadIdx.x;
    int e0 = blockIdx.x * EPB;
    int m = n_edges - e0;
    if (m > EPB) m = EPB;
    int mf4 = m * VECS_PER_EDGE;

    // Load x, apply switch. src(+) goes out immediately via red.v4 from regs;
    // -xw is staged to SMEM for the TMA dst reduce.
    #pragma unroll
    for (int k = 0; k < 3; k++) {
        int j = k * 256 + tid;                 // 0..767
        if (j < mf4) {
            int el = j / VECS_PER_EDGE;        // local edge 0..63
            int c  = j - el * VECS_PER_EDGE;   // 0..11
            int e  = e0 + el;
            float s = __ldg(sw + e);
            float4 v = __ldcs(x4 + (size_t)e * VECS_PER_EDGE + c);
            float ax = v.x * s, ay = v.y * s, az = v.z * s, aw = v.w * s;

            int srcn = __ldg(esrc + e);
            red_v4(out + (size_t)srcn * D_FEAT + (size_t)c * 4, ax, ay, az, aw);

            s_neg[j] = make_float4(-ax, -ay, -az, -aw);
        }
    }
    __syncthreads();
    asm volatile("fence.proxy.async.shared::cta;" ::: "memory");

    // dst(-) endpoint: one 192B TMA bulk reduce per edge from SMEM.
    if (tid < EPB) {
        if (tid < m) {
            int node = __ldg(edst + e0 + tid);
            uint32_t saddr =
                (uint32_t)__cvta_generic_to_shared(s_neg + tid * VECS_PER_EDGE);
            float* gaddr = out + (size_t)node * D_FEAT;
            asm volatile(
                "cp.reduce.async.bulk.global.shared::cta.bulk_group.add.f32 "
                "[%0], [%1], 192;"
                :: "l"(gaddr), "r"(saddr) : "memory");
        }
        asm volatile("cp.async.bulk.commit_group;" ::: "memory");
        // SMEM must stay live until the TMA engine has read it.
        asm volatile("cp.async.bulk.wait_group.read 0;" ::: "memory");
    }
}

extern "C" void kernel_launch(void* const* d_in, const int* in_sizes, int n_in,
                              void* d_out, int out_size) {
    const float4* x4  = (const float4*)d_in[0];   // x [E, 48] fp32
    const float*  sw  = (const float*)d_in[1];    // switch [E]
    const int*    src = (const int*)d_in[2];      // edge_src [E]
    const int*    dst = (const int*)d_in[3];      // edge_dst [E]
    float*        out = (float*)d_out;            // [nat, 48] fp32

    int n_edges = in_sizes[1];

    cudaMemsetAsync(out, 0, (size_t)out_size * sizeof(float));

    int n_blocks = (n_edges + EPB - 1) / EPB;     // 25000 for E=1.6M
    scatter_hybrid_kernel<<<n_blocks, 256>>>(x4, sw, src, dst, out, n_edges);
}

// round 8
// speedup vs baseline: 1.0293x; 1.0194x over previous
#include <cuda_runtime.h>
#include <cstdint>

// out[nat, 48] = segment_sum(x*switch, src) - segment_sum(x*switch, dst)
// E = 1.6M, D = 48, nat = 50k.
// Floor analysis (R4-R7): all delivery paths (REDG / TMA bulk-reduce / hybrid)
// funnel through per-SM L1TEX; 614 MB RMW at 16B-max vector red granularity is
// the binding constraint (~85% L1TEX across 4 distinct architectures).
// This round: trimmed R4 winner — 32-bit offset math, 128-thread blocks,
// interleaved red issue, float2/int2 scalar loads, streaming x loads.

#define D_FEAT 48
#define VECS_PER_EDGE (D_FEAT / 4)   // 12

__device__ __forceinline__ void red_v4(float* p, float a, float b, float c, float d) {
    asm volatile("red.global.add.v4.f32 [%0], {%1,%2,%3,%4};"
                 :: "l"(p), "f"(a), "f"(b), "f"(c), "f"(d) : "memory");
}

__global__ void __launch_bounds__(128)
scatter_edges_kernel(const float4* __restrict__ x4,
                     const float2* __restrict__ sw2,
                     const int2* __restrict__ esrc2,
                     const int2* __restrict__ edst2,
                     float* __restrict__ out,
                     int n_pairs) {
    unsigned t = blockIdx.x * 128u + threadIdx.x;
    unsigned total = (unsigned)n_pairs * VECS_PER_EDGE;
    if (t >= total) return;

    unsigned g = t / VECS_PER_EDGE;        // edge pair: edges 2g, 2g+1
    unsigned c = t - g * VECS_PER_EDGE;    // 0..11

    // Paired scalar loads: 1 wavefront each across the 12-lane group
    float2 s  = __ldg(sw2 + g);
    int2  src = __ldg(esrc2 + g);
    int2  dst = __ldg(edst2 + g);

    // Front-load x (streaming; zero reuse)
    unsigned base = g * (2 * VECS_PER_EDGE) + c;
    float4 v0 = __ldcs(x4 + base);
    float4 v1 = __ldcs(x4 + base + VECS_PER_EDGE);

    float ax = v0.x * s.x, ay = v0.y * s.x, az = v0.z * s.x, aw = v0.w * s.x;
    float bx = v1.x * s.y, by = v1.y * s.y, bz = v1.z * s.y, bw = v1.w * s.y;

    // 32-bit output offsets (max 50k*48 = 2.4M < 2^32)
    unsigned co = c * 4u;
    unsigned o_s0 = (unsigned)src.x * D_FEAT + co;
    unsigned o_d0 = (unsigned)dst.x * D_FEAT + co;
    unsigned o_s1 = (unsigned)src.y * D_FEAT + co;
    unsigned o_d1 = (unsigned)dst.y * D_FEAT + co;

    // Interleave: consecutive reds hit independent lines
    red_v4(out + o_s0,  ax,  ay,  az,  aw);
    red_v4(out + o_d0, -ax, -ay, -az, -aw);
    red_v4(out + o_s1,  bx,  by,  bz,  bw);
    red_v4(out + o_d1, -bx, -by, -bz, -bw);
}

extern "C" void kernel_launch(void* const* d_in, const int* in_sizes, int n_in,
                              void* d_out, int out_size) {
    const float4* x4  = (const float4*)d_in[0];   // x [E, 48] fp32
    const float2* sw2 = (const float2*)d_in[1];   // switch [E]
    const int2*   src = (const int2*)d_in[2];     // edge_src [E]
    const int2*   dst = (const int2*)d_in[3];     // edge_dst [E]
    float*        out = (float*)d_out;            // [nat, 48] fp32

    int n_edges = in_sizes[1];
    int n_pairs = n_edges / 2;                    // E = 1.6M, even

    cudaMemsetAsync(out, 0, (size_t)out_size * sizeof(float));

    unsigned total = (unsigned)n_pairs * VECS_PER_EDGE;
    scatter_edges_kernel<<<(total + 127) / 128, 128>>>(x4, sw2, src, dst, out, n_pairs);
}